// round 1
// baseline (speedup 1.0000x reference)
#include <cuda_runtime.h>
#include <cstdint>

#define BB 128
#define HH 1024
#define LL 256
#define NN 64

// Scratch (device globals: no allocations allowed in kernel_launch)
__device__ float g_k[HH * LL];                      // 1 MB  : S4D conv kernel (H,L)
__device__ float g_Wt[2 * HH * HH];                 // 8 MB  : W_out rounded to tf32
__device__ float g_y[(size_t)BB * HH * LL];         // 128 MB: post-gelu activations (tf32-rounded)

// ---------------------------------------------------------------------------
// helpers
// ---------------------------------------------------------------------------
__device__ __forceinline__ float tf32_round(float f) {
    uint32_t u;
    asm("cvt.rna.tf32.f32 %0, %1;" : "=r"(u) : "f"(f));
    return __uint_as_float(u);
}
__device__ __forceinline__ uint32_t fbits(float f) { return __float_as_uint(f); }

__device__ __forceinline__ void mma_tf32(float c[4], const uint32_t a[4], uint32_t b0, uint32_t b1) {
    asm volatile(
        "mma.sync.aligned.m16n8k8.row.col.f32.tf32.tf32.f32 "
        "{%0,%1,%2,%3}, {%4,%5,%6,%7}, {%8,%9}, {%0,%1,%2,%3};"
        : "+f"(c[0]), "+f"(c[1]), "+f"(c[2]), "+f"(c[3])
        : "r"(a[0]), "r"(a[1]), "r"(a[2]), "r"(a[3]), "r"(b0), "r"(b1));
}

__device__ __forceinline__ float gelu_tanh(float v) {
    float t = tanhf(0.7978845608028654f * (v + 0.044715f * v * v * v));
    return 0.5f * v * (1.0f + t);
}

// ---------------------------------------------------------------------------
// Kernel 1: S4D kernel materialization  k[h,l] = 2*Re(sum_n Cdisc * exp(dtA*l))
// one block per head h, 256 threads (one per l)
// ---------------------------------------------------------------------------
__global__ __launch_bounds__(256) void k_kernel(
    const float* __restrict__ log_dt, const float* __restrict__ A_real_log,
    const float* __restrict__ A_imag, const float* __restrict__ C_re,
    const float* __restrict__ C_im) {
    int h = blockIdx.x;
    __shared__ float sCr[NN], sCi[NN], sAr[NN], sAi[NN];   // Cdisc, dtA
    int tid = threadIdx.x;
    if (tid < NN) {
        float dt = expf(log_dt[h]);
        float Ar = -expf(A_real_log[h * NN + tid]);
        float Ai = A_imag[h * NN + tid];
        float dAr = Ar * dt, dAi = Ai * dt;
        float er = expf(dAr), sv, cv;
        sincosf(dAi, &sv, &cv);
        float Exr = er * cv - 1.0f;          // exp(dtA) - 1 (real)
        float Exi = er * sv;                 // (imag)
        float cr = C_re[h * NN + tid], ci = C_im[h * NN + tid];
        float nr = cr * Exr - ci * Exi;      // C*(exp(dtA)-1)
        float ni = cr * Exi + ci * Exr;
        float den = 1.0f / (Ar * Ar + Ai * Ai);
        sCr[tid] = (nr * Ar + ni * Ai) * den;   // / A
        sCi[tid] = (ni * Ar - nr * Ai) * den;
        sAr[tid] = dAr;
        sAi[tid] = dAi;
    }
    __syncthreads();
    float l = (float)tid;
    float acc = 0.0f;
#pragma unroll 4
    for (int n = 0; n < NN; n++) {
        float mag = expf(sAr[n] * l);
        float sv, cv;
        sincosf(sAi[n] * l, &sv, &cv);
        acc += sCr[n] * (mag * cv) - sCi[n] * (mag * sv);
    }
    g_k[h * LL + tid] = 2.0f * acc;
}

// ---------------------------------------------------------------------------
// Kernel 2: round W_out to tf32 precision once
// ---------------------------------------------------------------------------
__global__ __launch_bounds__(256) void wprep_kernel(const float* __restrict__ W) {
    int i = blockIdx.x * 256 + threadIdx.x;
    if (i < 2 * HH * HH) g_Wt[i] = tf32_round(W[i]);
}

// ---------------------------------------------------------------------------
// Kernel 3: causal conv + D-skip + gelu, writes tf32-rounded activations.
// block = (1 head h, 4 batches). Each thread computes 4 consecutive outputs
// with a sliding 4-register window over a zero-padded, bank-swizzled k row.
// y[l] = sum_{s<=l} x[s]*k[l-s] + D*x[l]  -> gelu
// ---------------------------------------------------------------------------
#define KIDX(i) ((i) + ((i) >> 5))   // swizzle: stride-4 lane access conflict-free

__global__ __launch_bounds__(256) void conv_kernel(const float* __restrict__ x,
                                                   const float* __restrict__ D) {
    __shared__ float kp[528];          // [0..255]=0 pad, [256..511]=k (swizzled)
    __shared__ float xs[4][LL];
    int h = blockIdx.x >> 5;
    int b0 = (blockIdx.x & 31) << 2;
    int tid = threadIdx.x;

    kp[KIDX(tid)] = 0.0f;
    kp[KIDX(256 + tid)] = g_k[h * LL + tid];
#pragma unroll
    for (int j = 0; j < 4; j++)
        xs[j][tid] = x[((size_t)(b0 + j) * HH + h) * LL + tid];
    __syncthreads();

    int row = tid >> 6;
    int l0 = (tid & 63) << 2;
    const float* xr = xs[row];
    float Dv = D[h];
    float a0 = Dv * xr[l0 + 0];
    float a1 = Dv * xr[l0 + 1];
    float a2 = Dv * xr[l0 + 2];
    float a3 = Dv * xr[l0 + 3];

    int B0 = 256 + l0;
    float r0 = kp[KIDX(B0 + 0)];
    float r1 = kp[KIDX(B0 + 1)];
    float r2 = kp[KIDX(B0 + 2)];
    float r3 = kp[KIDX(B0 + 3)];

#pragma unroll 4
    for (int s4 = 0; s4 < LL; s4 += 4) {
        float x0 = xr[s4 + 0];
        a0 += x0 * r0; a1 += x0 * r1; a2 += x0 * r2; a3 += x0 * r3;
        r3 = kp[KIDX(B0 - s4 - 1)];
        float x1 = xr[s4 + 1];
        a0 += x1 * r3; a1 += x1 * r0; a2 += x1 * r1; a3 += x1 * r2;
        r2 = kp[KIDX(B0 - s4 - 2)];
        float x2 = xr[s4 + 2];
        a0 += x2 * r2; a1 += x2 * r3; a2 += x2 * r0; a3 += x2 * r1;
        r1 = kp[KIDX(B0 - s4 - 3)];
        float x3 = xr[s4 + 3];
        a0 += x3 * r1; a1 += x3 * r2; a2 += x3 * r3; a3 += x3 * r0;
        r0 = kp[KIDX(B0 - s4 - 4)];
    }

    float4 v;
    v.x = tf32_round(gelu_tanh(a0));
    v.y = tf32_round(gelu_tanh(a1));
    v.z = tf32_round(gelu_tanh(a2));
    v.w = tf32_round(gelu_tanh(a3));
    *(float4*)&g_y[((size_t)(b0 + row) * HH + h) * LL + l0] = v;
}

// ---------------------------------------------------------------------------
// Kernel 4: out[b,h,l] = (W[h,:].y + bias[h]) * sigmoid(W[h+H,:].y + bias[h+H])
// Per block: 64 h_out x 64 l for one batch b (two W tiles so GLU fuses).
// tf32 mma.sync m16n8k8, fp32 accumulate. 8 warps = 4(m) x 2(n).
// ---------------------------------------------------------------------------
__global__ __launch_bounds__(256) void gemm_glu_kernel(const float* __restrict__ bias,
                                                       float* __restrict__ out) {
    __shared__ __align__(16) float Was[64 * 20];   // [m][k] ld=20 (pad)
    __shared__ __align__(16) float Wbs[64 * 20];
    __shared__ __align__(16) float Ys[16 * 72];    // [k][n] ld=72 (pad)

    int b = blockIdx.z;
    int h0 = blockIdx.y * 64;
    int l0 = blockIdx.x * 64;
    int tid = threadIdx.x;
    int lane = tid & 31;
    int wid = tid >> 5;
    int wm = wid & 3;        // 0..3 : 16 h_out each
    int wn = wid >> 2;       // 0..1 : 32 l each

    float ca[4][4];          // [n8-tile][reg], "a" half (rows h0..)
    float cb[4][4];          // "b" half (rows h0+1024..)
#pragma unroll
    for (int t = 0; t < 4; t++)
#pragma unroll
        for (int r = 0; r < 4; r++) { ca[t][r] = 0.0f; cb[t][r] = 0.0f; }

    const float* Yb = g_y + (size_t)b * HH * LL;

    int wrow = tid >> 2, wkq = (tid & 3) << 2;     // W tile loads
    int yrow = tid >> 4, ynq = (tid & 15) << 2;    // Y tile loads

    for (int k0 = 0; k0 < HH; k0 += 16) {
        float4 va = *(const float4*)&g_Wt[(size_t)(h0 + wrow) * HH + k0 + wkq];
        *(float4*)&Was[wrow * 20 + wkq] = va;
        float4 vb = *(const float4*)&g_Wt[(size_t)(h0 + wrow + HH) * HH + k0 + wkq];
        *(float4*)&Wbs[wrow * 20 + wkq] = vb;
        float4 vy = *(const float4*)&Yb[(k0 + yrow) * LL + l0 + ynq];
        *(float4*)&Ys[yrow * 72 + ynq] = vy;
        __syncthreads();

#pragma unroll
        for (int ks = 0; ks < 2; ks++) {
            int kk = ks * 8;
            int ar = wm * 16 + (lane >> 2);
            int ac = kk + (lane & 3);
            uint32_t aa[4], ab[4];
            aa[0] = fbits(Was[ar * 20 + ac]);
            aa[1] = fbits(Was[(ar + 8) * 20 + ac]);
            aa[2] = fbits(Was[ar * 20 + ac + 4]);
            aa[3] = fbits(Was[(ar + 8) * 20 + ac + 4]);
            ab[0] = fbits(Wbs[ar * 20 + ac]);
            ab[1] = fbits(Wbs[(ar + 8) * 20 + ac]);
            ab[2] = fbits(Wbs[ar * 20 + ac + 4]);
            ab[3] = fbits(Wbs[(ar + 8) * 20 + ac + 4]);
#pragma unroll
            for (int t = 0; t < 4; t++) {
                int bc = wn * 32 + t * 8 + (lane >> 2);
                int br = kk + (lane & 3);
                uint32_t bf0 = fbits(Ys[br * 72 + bc]);
                uint32_t bf1 = fbits(Ys[(br + 4) * 72 + bc]);
                mma_tf32(ca[t], aa, bf0, bf1);
                mma_tf32(cb[t], ab, bf0, bf1);
            }
        }
        __syncthreads();
    }

    // epilogue: bias + GLU, coalesced float2 stores
    int r = lane >> 2;
    int c2 = (lane & 3) << 1;
    int hh = h0 + wm * 16 + r;
    float ba0 = bias[hh],     bb0 = bias[hh + HH];
    float ba8 = bias[hh + 8], bb8 = bias[hh + 8 + HH];
    size_t ob0 = ((size_t)b * HH + hh) * LL;
    size_t ob8 = ob0 + (size_t)8 * LL;
#pragma unroll
    for (int t = 0; t < 4; t++) {
        int ll = l0 + wn * 32 + t * 8 + c2;
        float av, bv;
        float2 w0, w8;
        av = ca[t][0] + ba0; bv = cb[t][0] + bb0;
        w0.x = av * (1.0f / (1.0f + expf(-bv)));
        av = ca[t][1] + ba0; bv = cb[t][1] + bb0;
        w0.y = av * (1.0f / (1.0f + expf(-bv)));
        av = ca[t][2] + ba8; bv = cb[t][2] + bb8;
        w8.x = av * (1.0f / (1.0f + expf(-bv)));
        av = ca[t][3] + ba8; bv = cb[t][3] + bb8;
        w8.y = av * (1.0f / (1.0f + expf(-bv)));
        *(float2*)&out[ob0 + ll] = w0;
        *(float2*)&out[ob8 + ll] = w8;
    }
}

// ---------------------------------------------------------------------------
extern "C" void kernel_launch(void* const* d_in, const int* in_sizes, int n_in,
                              void* d_out, int out_size) {
    const float* x          = (const float*)d_in[0];
    const float* log_dt     = (const float*)d_in[1];
    const float* A_real_log = (const float*)d_in[2];
    const float* A_imag     = (const float*)d_in[3];
    const float* C_re       = (const float*)d_in[4];
    const float* C_im       = (const float*)d_in[5];
    const float* D          = (const float*)d_in[6];
    const float* W_out      = (const float*)d_in[7];
    const float* b_out      = (const float*)d_in[8];
    float* out = (float*)d_out;

    k_kernel<<<HH, 256>>>(log_dt, A_real_log, A_imag, C_re, C_im);
    wprep_kernel<<<(2 * HH * HH) / 256, 256>>>(W_out);
    conv_kernel<<<HH * (BB / 4), 256>>>(x, D);
    gemm_glu_kernel<<<dim3(LL / 64, HH / 64, BB), 256>>>(b_out, out);
}